// round 3
// baseline (speedup 1.0000x reference)
#include <cuda_runtime.h>
#include <math.h>

#define TT 1024
#define HH 2048
#define II 1024
#define EE 32

// ---------------- scratch (device globals; no allocs) ----------------
__device__ __align__(256) int   g_top2_idx[TT * 2];
__device__ __align__(256) float g_top2_w[TT * 2];
__device__ __align__(256) int   g_cnt[EE];
__device__ __align__(256) int   g_toklist[EE * TT];          // packed (t<<1)|slot
__device__ __align__(256) float g_act[TT * 2 * II];          // 8 MB
__device__ __align__(256) float g_partial[2 * TT * HH];      // 16 MB

// ---------------- packed f32x2 helpers (sm_103a) ----------------
__device__ __forceinline__ unsigned long long pack2(float v) {
    unsigned long long r; unsigned u = __float_as_uint(v);
    asm("mov.b64 %0, {%1, %1};" : "=l"(r) : "r"(u));
    return r;
}
__device__ __forceinline__ void fma2(unsigned long long& acc,
                                     unsigned long long a, unsigned long long b) {
    asm("fma.rn.f32x2 %0, %1, %2, %0;" : "+l"(acc) : "l"(a), "l"(b));
}
__device__ __forceinline__ float2 u2f(unsigned long long v) {
    unsigned lo, hi;
    asm("mov.b64 {%0, %1}, %2;" : "=r"(lo), "=r"(hi) : "l"(v));
    float2 f; f.x = __uint_as_float(lo); f.y = __uint_as_float(hi);
    return f;
}

// ---------------- 1. router: logits -> top2 weights ----------------
__global__ __launch_bounds__(256) void router_k(const float* __restrict__ x,
                                                const float* __restrict__ gw) {
    __shared__ float xs[HH];
    __shared__ float lg[EE];
    int t = blockIdx.x;
    const float* xr = x + (size_t)t * HH;
    for (int i = threadIdx.x; i < HH; i += 256) xs[i] = xr[i];
    __syncthreads();
    int w = threadIdx.x >> 5, lane = threadIdx.x & 31;
    for (int e = w; e < EE; e += 8) {
        const float* g = gw + (size_t)e * HH;
        float s = 0.f;
        for (int h = lane; h < HH; h += 32) s += xs[h] * g[h];
        #pragma unroll
        for (int o = 16; o; o >>= 1) s += __shfl_xor_sync(0xffffffffu, s, o);
        if (!lane) lg[e] = s;
    }
    __syncthreads();
    if (threadIdx.x == 0) {
        float m1 = -1e30f, m2 = -1e30f; int i1 = 0, i2 = 1;
        for (int e = 0; e < EE; e++) {
            float v = lg[e];
            if (v > m1)      { m2 = m1; i2 = i1; m1 = v; i1 = e; }
            else if (v > m2) { m2 = v; i2 = e; }
        }
        // renormalized top-2 softmax weights: global denominator cancels
        float q = expf(m2 - m1);
        float w1 = 1.f / (1.f + q);
        g_top2_idx[2 * t] = i1;  g_top2_idx[2 * t + 1] = i2;
        g_top2_w[2 * t] = w1;    g_top2_w[2 * t + 1] = 1.f - w1;
    }
}

// ---------------- 2. build per-expert token lists ----------------
__global__ void zero_k() { if (threadIdx.x < EE) g_cnt[threadIdx.x] = 0; }

__global__ void scatter_k() {
    int t = blockIdx.x * blockDim.x + threadIdx.x;
    if (t >= TT) return;
    #pragma unroll
    for (int s = 0; s < 2; s++) {
        int e = g_top2_idx[2 * t + s];
        int pos = atomicAdd(&g_cnt[e], 1);
        g_toklist[e * TT + pos] = (t << 1) | s;
    }
}

// ---------------- 3. grouped gate+up GEMM + SwiGLU ----------------
// grid: (E, I/64, T/64 max M-tiles); block 256; tile [64 tok][64 i] BK=32
__global__ __launch_bounds__(256) void gateup_k(const float* __restrict__ x,
                                                const float* __restrict__ gw,
                                                const float* __restrict__ uw) {
    int e = blockIdx.x;
    int cnt = g_cnt[e];
    int m0 = blockIdx.z << 6;
    if (m0 >= cnt) return;
    int i0 = blockIdx.y << 6;

    __shared__ __align__(16) float xs[32][64];
    __shared__ __align__(16) float gs[32][64];
    __shared__ __align__(16) float us[32][64];
    __shared__ int   stok[64];
    __shared__ float swt[64];

    int tid = threadIdx.x;
    if (tid < 64) {
        int m = m0 + tid;
        if (m < cnt) { int p = g_toklist[e * TT + m]; stok[tid] = p; swt[tid] = g_top2_w[p]; }
        else         { stok[tid] = 0; swt[tid] = 0.f; }
    }
    __syncthreads();

    int lrow = tid >> 2;        // 0..63 : staged row
    int lq   = tid & 3;         // 0..3  : 16B chunk within 64B half
    const float* xrow = x  + (size_t)(stok[lrow] >> 1) * HH;
    const float* grow = gw + ((size_t)e * II + i0 + lrow) * HH;
    const float* urow = uw + ((size_t)e * II + i0 + lrow) * HH;

    int r0 = (tid >> 4) << 2;   // 4 token rows
    int c0 = (tid & 15) << 2;   // 4 i cols

    unsigned long long ga[4][2], ua[4][2];
    #pragma unroll
    for (int i = 0; i < 4; i++) { ga[i][0] = 0; ga[i][1] = 0; ua[i][0] = 0; ua[i][1] = 0; }

    for (int k0 = 0; k0 < HH; k0 += 32) {
        float4 xv0 = *(const float4*)(xrow + k0 + lq * 4);
        float4 xv1 = *(const float4*)(xrow + k0 + 16 + lq * 4);
        float4 gv0 = *(const float4*)(grow + k0 + lq * 4);
        float4 gv1 = *(const float4*)(grow + k0 + 16 + lq * 4);
        float4 uv0 = *(const float4*)(urow + k0 + lq * 4);
        float4 uv1 = *(const float4*)(urow + k0 + 16 + lq * 4);
        __syncthreads();
        int kk = lq * 4;
        xs[kk + 0][lrow] = xv0.x; xs[kk + 1][lrow] = xv0.y; xs[kk + 2][lrow] = xv0.z; xs[kk + 3][lrow] = xv0.w;
        xs[kk + 16][lrow] = xv1.x; xs[kk + 17][lrow] = xv1.y; xs[kk + 18][lrow] = xv1.z; xs[kk + 19][lrow] = xv1.w;
        gs[kk + 0][lrow] = gv0.x; gs[kk + 1][lrow] = gv0.y; gs[kk + 2][lrow] = gv0.z; gs[kk + 3][lrow] = gv0.w;
        gs[kk + 16][lrow] = gv1.x; gs[kk + 17][lrow] = gv1.y; gs[kk + 18][lrow] = gv1.z; gs[kk + 19][lrow] = gv1.w;
        us[kk + 0][lrow] = uv0.x; us[kk + 1][lrow] = uv0.y; us[kk + 2][lrow] = uv0.z; us[kk + 3][lrow] = uv0.w;
        us[kk + 16][lrow] = uv1.x; us[kk + 17][lrow] = uv1.y; us[kk + 18][lrow] = uv1.z; us[kk + 19][lrow] = uv1.w;
        __syncthreads();
        #pragma unroll
        for (int k = 0; k < 32; k++) {
            float4 xa = *(const float4*)&xs[k][r0];
            longlong2 gb = *(const longlong2*)&gs[k][c0];
            longlong2 ub = *(const longlong2*)&us[k][c0];
            unsigned long long b0 = (unsigned long long)gb.x, b1 = (unsigned long long)gb.y;
            unsigned long long d0 = (unsigned long long)ub.x, d1 = (unsigned long long)ub.y;
            unsigned long long a0 = pack2(xa.x), a1 = pack2(xa.y), a2 = pack2(xa.z), a3 = pack2(xa.w);
            fma2(ga[0][0], a0, b0); fma2(ga[0][1], a0, b1); fma2(ua[0][0], a0, d0); fma2(ua[0][1], a0, d1);
            fma2(ga[1][0], a1, b0); fma2(ga[1][1], a1, b1); fma2(ua[1][0], a1, d0); fma2(ua[1][1], a1, d1);
            fma2(ga[2][0], a2, b0); fma2(ga[2][1], a2, b1); fma2(ua[2][0], a2, d0); fma2(ua[2][1], a2, d1);
            fma2(ga[3][0], a3, b0); fma2(ga[3][1], a3, b1); fma2(ua[3][0], a3, d0); fma2(ua[3][1], a3, d1);
        }
    }

    #pragma unroll
    for (int ri = 0; ri < 4; ri++) {
        int m = m0 + r0 + ri;
        if (m < cnt) {
            int p = stok[r0 + ri];
            float wgt = swt[r0 + ri];
            float2 g0 = u2f(ga[ri][0]), g1 = u2f(ga[ri][1]);
            float2 u0 = u2f(ua[ri][0]), u1 = u2f(ua[ri][1]);
            float4 o;
            o.x = (g0.x / (1.f + expf(-g0.x))) * u0.x * wgt;
            o.y = (g0.y / (1.f + expf(-g0.y))) * u0.y * wgt;
            o.z = (g1.x / (1.f + expf(-g1.x))) * u1.x * wgt;
            o.w = (g1.y / (1.f + expf(-g1.y))) * u1.y * wgt;
            *(float4*)(g_act + (size_t)p * II + i0 + c0) = o;
        }
    }
}

// ---------------- 4. grouped down GEMM -> slot partials ----------------
// grid: (E, H/64, T/64); block 256; tile [64 tok][64 h] BK=32 over I
__global__ __launch_bounds__(256) void down_k(const float* __restrict__ dw) {
    int e = blockIdx.x;
    int cnt = g_cnt[e];
    int m0 = blockIdx.z << 6;
    if (m0 >= cnt) return;
    int h0 = blockIdx.y << 6;

    __shared__ __align__(16) float as_[32][64];
    __shared__ __align__(16) float bs[32][64];
    __shared__ int stok[64];

    int tid = threadIdx.x;
    if (tid < 64) {
        int m = m0 + tid;
        stok[tid] = (m < cnt) ? g_toklist[e * TT + m] : 0;
    }
    __syncthreads();

    int lrow = tid >> 2, lq = tid & 3;
    const float* arow = g_act + (size_t)stok[lrow] * II;
    const float* brow = dw + ((size_t)e * HH + h0 + lrow) * II;

    int r0 = (tid >> 4) << 2;
    int c0 = (tid & 15) << 2;

    unsigned long long acc[4][2];
    #pragma unroll
    for (int i = 0; i < 4; i++) { acc[i][0] = 0; acc[i][1] = 0; }

    for (int k0 = 0; k0 < II; k0 += 32) {
        float4 av0 = *(const float4*)(arow + k0 + lq * 4);
        float4 av1 = *(const float4*)(arow + k0 + 16 + lq * 4);
        float4 bv0 = *(const float4*)(brow + k0 + lq * 4);
        float4 bv1 = *(const float4*)(brow + k0 + 16 + lq * 4);
        __syncthreads();
        int kk = lq * 4;
        as_[kk + 0][lrow] = av0.x; as_[kk + 1][lrow] = av0.y; as_[kk + 2][lrow] = av0.z; as_[kk + 3][lrow] = av0.w;
        as_[kk + 16][lrow] = av1.x; as_[kk + 17][lrow] = av1.y; as_[kk + 18][lrow] = av1.z; as_[kk + 19][lrow] = av1.w;
        bs[kk + 0][lrow] = bv0.x; bs[kk + 1][lrow] = bv0.y; bs[kk + 2][lrow] = bv0.z; bs[kk + 3][lrow] = bv0.w;
        bs[kk + 16][lrow] = bv1.x; bs[kk + 17][lrow] = bv1.y; bs[kk + 18][lrow] = bv1.z; bs[kk + 19][lrow] = bv1.w;
        __syncthreads();
        #pragma unroll
        for (int k = 0; k < 32; k++) {
            float4 xa = *(const float4*)&as_[k][r0];
            longlong2 bb = *(const longlong2*)&bs[k][c0];
            unsigned long long b0 = (unsigned long long)bb.x, b1 = (unsigned long long)bb.y;
            unsigned long long a0 = pack2(xa.x), a1 = pack2(xa.y), a2 = pack2(xa.z), a3 = pack2(xa.w);
            fma2(acc[0][0], a0, b0); fma2(acc[0][1], a0, b1);
            fma2(acc[1][0], a1, b0); fma2(acc[1][1], a1, b1);
            fma2(acc[2][0], a2, b0); fma2(acc[2][1], a2, b1);
            fma2(acc[3][0], a3, b0); fma2(acc[3][1], a3, b1);
        }
    }

    #pragma unroll
    for (int ri = 0; ri < 4; ri++) {
        int m = m0 + r0 + ri;
        if (m < cnt) {
            int p = stok[r0 + ri];
            int t = p >> 1, s = p & 1;
            float2 a0 = u2f(acc[ri][0]), a1 = u2f(acc[ri][1]);
            float4 o; o.x = a0.x; o.y = a0.y; o.z = a1.x; o.w = a1.y;
            *(float4*)(g_partial + (size_t)s * TT * HH + (size_t)t * HH + h0 + c0) = o;
        }
    }
}

// ---------------- 5. combine the two slot partials ----------------
__global__ void combine_k(float* __restrict__ out) {
    int i = blockIdx.x * 256 + threadIdx.x;
    if (i < TT * HH) out[i] = g_partial[i] + g_partial[TT * HH + i];
}

// ---------------- launch ----------------
extern "C" void kernel_launch(void* const* d_in, const int* in_sizes, int n_in,
                              void* d_out, int out_size) {
    const float* x      = (const float*)d_in[0];
    const float* gate_w = (const float*)d_in[1];
    const float* gpw    = (const float*)d_in[2];
    const float* upw    = (const float*)d_in[3];
    const float* dpw    = (const float*)d_in[4];
    float* out = (float*)d_out;

    router_k<<<TT, 256>>>(x, gate_w);
    zero_k<<<1, 32>>>();
    scatter_k<<<(TT + 255) / 256, 256>>>();
    gateup_k<<<dim3(EE, II / 64, TT / 64), 256>>>(x, gpw, upw);
    down_k<<<dim3(EE, HH / 64, TT / 64), 256>>>(dpw);
    combine_k<<<(TT * HH + 255) / 256, 256>>>(out);
}

// round 5
// speedup vs baseline: 2.3484x; 2.3484x over previous
#include <cuda_runtime.h>
#include <math.h>
#include <stdint.h>

#define TT 1024
#define HH 2048
#define II 1024
#define EE 32

// ---------------- scratch (device globals; no allocs) ----------------
__device__ __align__(256) int   g_top2_idx[TT * 2];
__device__ __align__(256) float g_top2_w[TT * 2];
__device__ __align__(256) int   g_cnt[EE];
__device__ __align__(256) int   g_toklist[EE * TT];          // packed (t<<1)|slot
__device__ __align__(256) float g_act[TT * 2 * II];          // 8 MB
__device__ __align__(256) float g_partial[2 * TT * HH];      // 16 MB

// ---------------- tf32 mma.sync helpers (sm_80+ ISA, valid on sm_103 base) ----
__device__ __forceinline__ uint32_t f2tf(float f) {
    uint32_t r; asm("cvt.rna.tf32.f32 %0, %1;" : "=r"(r) : "f"(f)); return r;
}
__device__ __forceinline__ void mma1688(float* d, const uint32_t* a, const uint32_t* b) {
    asm volatile(
        "mma.sync.aligned.m16n8k8.row.col.f32.tf32.tf32.f32 "
        "{%0,%1,%2,%3}, {%4,%5,%6,%7}, {%8,%9}, {%0,%1,%2,%3};"
        : "+f"(d[0]), "+f"(d[1]), "+f"(d[2]), "+f"(d[3])
        : "r"(a[0]), "r"(a[1]), "r"(a[2]), "r"(a[3]), "r"(b[0]), "r"(b[1]));
}
__device__ __forceinline__ uint4 cvt4(float4 v) {
    uint4 o; o.x = f2tf(v.x); o.y = f2tf(v.y); o.z = f2tf(v.z); o.w = f2tf(v.w);
    return o;
}

#define LDW 36   // 32 k-floats + 4 pad -> bank shift 4 per row, conflict-free frags

// ---------------- 1. router: logits -> top2 weights (exact fp32) ----------------
__global__ __launch_bounds__(256) void router_k(const float* __restrict__ x,
                                                const float* __restrict__ gw) {
    __shared__ float xs[HH];
    __shared__ float lg[EE];
    int t = blockIdx.x;
    const float* xr = x + (size_t)t * HH;
    for (int i = threadIdx.x; i < HH; i += 256) xs[i] = xr[i];
    __syncthreads();
    int w = threadIdx.x >> 5, lane = threadIdx.x & 31;
    for (int e = w; e < EE; e += 8) {
        const float* g = gw + (size_t)e * HH;
        float s = 0.f;
        for (int h = lane; h < HH; h += 32) s += xs[h] * g[h];
        #pragma unroll
        for (int o = 16; o; o >>= 1) s += __shfl_xor_sync(0xffffffffu, s, o);
        if (!lane) lg[e] = s;
    }
    __syncthreads();
    if (threadIdx.x == 0) {
        float m1 = -1e30f, m2 = -1e30f; int i1 = 0, i2 = 1;
        for (int e = 0; e < EE; e++) {
            float v = lg[e];
            if (v > m1)      { m2 = m1; i2 = i1; m1 = v; i1 = e; }
            else if (v > m2) { m2 = v; i2 = e; }
        }
        float q = expf(m2 - m1);
        float w1 = 1.f / (1.f + q);
        g_top2_idx[2 * t] = i1;  g_top2_idx[2 * t + 1] = i2;
        g_top2_w[2 * t] = w1;    g_top2_w[2 * t + 1] = 1.f - w1;
    }
}

// ---------------- 2. per-expert token lists ----------------
__global__ void zero_k() { if (threadIdx.x < EE) g_cnt[threadIdx.x] = 0; }

__global__ void scatter_k() {
    int t = blockIdx.x * blockDim.x + threadIdx.x;
    if (t >= TT) return;
    #pragma unroll
    for (int s = 0; s < 2; s++) {
        int e = g_top2_idx[2 * t + s];
        int pos = atomicAdd(&g_cnt[e], 1);
        g_toklist[e * TT + pos] = (t << 1) | s;
    }
}

// ---------------- 3. gate+up grouped GEMM (tf32 mma.sync) ----------------
// grid (E, I/128, T/64); block 256 = 8 warps (2 m x 4 n), warp tile 32x32 per matrix.
__global__ __launch_bounds__(256) void gateup_mma(const float* __restrict__ x,
                                                  const float* __restrict__ gw,
                                                  const float* __restrict__ uw) {
    int e = blockIdx.x;
    int cnt = g_cnt[e];
    int m0 = blockIdx.z << 6;
    if (m0 >= cnt) return;
    int i0 = blockIdx.y << 7;

    __shared__ uint32_t xs[64 * LDW];    // A: [m][k] tf32
    __shared__ uint32_t gs[128 * LDW];   // gate W: [i][k] tf32
    __shared__ uint32_t us[128 * LDW];   // up W:   [i][k] tf32
    __shared__ int   stok[64];
    __shared__ float swt[64];

    int tid = threadIdx.x, wid = tid >> 5, lane = tid & 31;
    int g = lane >> 2, tig = lane & 3;
    int m_base = (wid >> 2) * 32;        // 0 or 32
    int n_base = (wid & 3) * 32;         // 0..96

    if (tid < 64) {
        int m = m0 + tid;
        if (m < cnt) { int p = g_toklist[e * TT + m]; stok[tid] = p; swt[tid] = g_top2_w[p]; }
        else         { stok[tid] = g_toklist[e * TT]; swt[tid] = 0.f; }
    }
    __syncthreads();

    // staging assignments: A 2x float4/thread, Bg 4x, Bu 4x per 32-k stage
    const float* ap[2]; uint32_t soa[2];
    #pragma unroll
    for (int c = 0; c < 2; c++) {
        int f = c * 256 + tid, row = f >> 3, q = f & 7;
        ap[c]  = x + (size_t)(stok[row] >> 1) * HH + q * 4;
        soa[c] = row * LDW + q * 4;
    }
    const float* gp[4]; const float* up_[4]; uint32_t sob[4];
    #pragma unroll
    for (int c = 0; c < 4; c++) {
        int f = c * 256 + tid, row = f >> 3, q = f & 7;
        gp[c]  = gw + ((size_t)e * II + i0 + row) * HH + q * 4;
        up_[c] = uw + ((size_t)e * II + i0 + row) * HH + q * 4;
        sob[c] = row * LDW + q * 4;
    }

    float accG[2][4][4], accU[2][4][4];
    #pragma unroll
    for (int mt = 0; mt < 2; mt++)
        #pragma unroll
        for (int nt = 0; nt < 4; nt++)
            #pragma unroll
            for (int j = 0; j < 4; j++) { accG[mt][nt][j] = 0.f; accU[mt][nt][j] = 0.f; }

    for (int it = 0; it < HH / 32; it++) {
        int k0 = it * 32;
        float4 av[2], gv[4], uv[4];
        #pragma unroll
        for (int c = 0; c < 2; c++) av[c] = *(const float4*)(ap[c] + k0);
        #pragma unroll
        for (int c = 0; c < 4; c++) { gv[c] = *(const float4*)(gp[c] + k0);
                                      uv[c] = *(const float4*)(up_[c] + k0); }
        __syncthreads();   // prior stage's mma reads done
        #pragma unroll
        for (int c = 0; c < 2; c++) *(uint4*)&xs[soa[c]] = cvt4(av[c]);
        #pragma unroll
        for (int c = 0; c < 4; c++) { *(uint4*)&gs[sob[c]] = cvt4(gv[c]);
                                      *(uint4*)&us[sob[c]] = cvt4(uv[c]); }
        __syncthreads();

        #pragma unroll
        for (int ks = 0; ks < 4; ks++) {
            int kk = ks * 8;
            uint32_t af[2][4];
            #pragma unroll
            for (int mt = 0; mt < 2; mt++) {
                int rb = m_base + mt * 16 + g;
                af[mt][0] = xs[rb * LDW + kk + tig];
                af[mt][1] = xs[(rb + 8) * LDW + kk + tig];
                af[mt][2] = xs[rb * LDW + kk + tig + 4];
                af[mt][3] = xs[(rb + 8) * LDW + kk + tig + 4];
            }
            #pragma unroll
            for (int nt = 0; nt < 4; nt++) {
                int cb = (n_base + nt * 8 + g) * LDW + kk + tig;
                uint32_t bg[2] = { gs[cb], gs[cb + 4] };
                uint32_t bu[2] = { us[cb], us[cb + 4] };
                #pragma unroll
                for (int mt = 0; mt < 2; mt++) {
                    mma1688(accG[mt][nt], af[mt], bg);
                    mma1688(accU[mt][nt], af[mt], bu);
                }
            }
        }
    }

    // fused SwiGLU + routing-weight epilogue
    #pragma unroll
    for (int mt = 0; mt < 2; mt++) {
        int r0 = m_base + mt * 16 + g;
        #pragma unroll
        for (int half = 0; half < 2; half++) {
            int rr = r0 + half * 8;
            if (m0 + rr < cnt) {
                int p = stok[rr]; float wgt = swt[rr];
                float* orow = g_act + (size_t)p * II + i0;
                #pragma unroll
                for (int nt = 0; nt < 4; nt++) {
                    float g0 = accG[mt][nt][half * 2], g1 = accG[mt][nt][half * 2 + 1];
                    float u0 = accU[mt][nt][half * 2], u1 = accU[mt][nt][half * 2 + 1];
                    float2 o;
                    o.x = (g0 / (1.f + expf(-g0))) * u0 * wgt;
                    o.y = (g1 / (1.f + expf(-g1))) * u1 * wgt;
                    *(float2*)(orow + n_base + nt * 8 + tig * 2) = o;
                }
            }
        }
    }
}

// ---------------- 4. down grouped GEMM (tf32 mma.sync) ----------------
// grid (E, H/128, T/64); same warp layout, single output matrix, K=I=1024.
__global__ __launch_bounds__(256) void down_mma(const float* __restrict__ dw) {
    int e = blockIdx.x;
    int cnt = g_cnt[e];
    int m0 = blockIdx.z << 6;
    if (m0 >= cnt) return;
    int h0 = blockIdx.y << 7;

    __shared__ uint32_t as_[64 * LDW];
    __shared__ uint32_t bs[128 * LDW];
    __shared__ int stok[64];

    int tid = threadIdx.x, wid = tid >> 5, lane = tid & 31;
    int g = lane >> 2, tig = lane & 3;
    int m_base = (wid >> 2) * 32;
    int n_base = (wid & 3) * 32;

    if (tid < 64) {
        int m = m0 + tid;
        stok[tid] = (m < cnt) ? g_toklist[e * TT + m] : g_toklist[e * TT];
    }
    __syncthreads();

    const float* ap[2]; uint32_t soa[2];
    #pragma unroll
    for (int c = 0; c < 2; c++) {
        int f = c * 256 + tid, row = f >> 3, q = f & 7;
        ap[c]  = g_act + (size_t)stok[row] * II + q * 4;
        soa[c] = row * LDW + q * 4;
    }
    const float* bp[4]; uint32_t sob[4];
    #pragma unroll
    for (int c = 0; c < 4; c++) {
        int f = c * 256 + tid, row = f >> 3, q = f & 7;
        bp[c]  = dw + ((size_t)e * HH + h0 + row) * II + q * 4;
        sob[c] = row * LDW + q * 4;
    }

    float acc[2][4][4];
    #pragma unroll
    for (int mt = 0; mt < 2; mt++)
        #pragma unroll
        for (int nt = 0; nt < 4; nt++)
            #pragma unroll
            for (int j = 0; j < 4; j++) acc[mt][nt][j] = 0.f;

    for (int it = 0; it < II / 32; it++) {
        int k0 = it * 32;
        float4 av[2], bv[4];
        #pragma unroll
        for (int c = 0; c < 2; c++) av[c] = *(const float4*)(ap[c] + k0);
        #pragma unroll
        for (int c = 0; c < 4; c++) bv[c] = *(const float4*)(bp[c] + k0);
        __syncthreads();
        #pragma unroll
        for (int c = 0; c < 2; c++) *(uint4*)&as_[soa[c]] = cvt4(av[c]);
        #pragma unroll
        for (int c = 0; c < 4; c++) *(uint4*)&bs[sob[c]] = cvt4(bv[c]);
        __syncthreads();

        #pragma unroll
        for (int ks = 0; ks < 4; ks++) {
            int kk = ks * 8;
            uint32_t af[2][4];
            #pragma unroll
            for (int mt = 0; mt < 2; mt++) {
                int rb = m_base + mt * 16 + g;
                af[mt][0] = as_[rb * LDW + kk + tig];
                af[mt][1] = as_[(rb + 8) * LDW + kk + tig];
                af[mt][2] = as_[rb * LDW + kk + tig + 4];
                af[mt][3] = as_[(rb + 8) * LDW + kk + tig + 4];
            }
            #pragma unroll
            for (int nt = 0; nt < 4; nt++) {
                int cb = (n_base + nt * 8 + g) * LDW + kk + tig;
                uint32_t bb[2] = { bs[cb], bs[cb + 4] };
                #pragma unroll
                for (int mt = 0; mt < 2; mt++) mma1688(acc[mt][nt], af[mt], bb);
            }
        }
    }

    #pragma unroll
    for (int mt = 0; mt < 2; mt++) {
        int r0 = m_base + mt * 16 + g;
        #pragma unroll
        for (int half = 0; half < 2; half++) {
            int rr = r0 + half * 8;
            if (m0 + rr < cnt) {
                int p = stok[rr];
                int t = p >> 1, s = p & 1;
                float* orow = g_partial + (size_t)s * TT * HH + (size_t)t * HH + h0;
                #pragma unroll
                for (int nt = 0; nt < 4; nt++) {
                    float2 o;
                    o.x = acc[mt][nt][half * 2];
                    o.y = acc[mt][nt][half * 2 + 1];
                    *(float2*)(orow + n_base + nt * 8 + tig * 2) = o;
                }
            }
        }
    }
}

// ---------------- 5. combine slot partials ----------------
__global__ void combine_k(float* __restrict__ out) {
    int i = blockIdx.x * 256 + threadIdx.x;
    if (i < TT * HH) out[i] = g_partial[i] + g_partial[TT * HH + i];
}

// ---------------- launch ----------------
extern "C" void kernel_launch(void* const* d_in, const int* in_sizes, int n_in,
                              void* d_out, int out_size) {
    const float* x      = (const float*)d_in[0];
    const float* gate_w = (const float*)d_in[1];
    const float* gpw    = (const float*)d_in[2];
    const float* upw    = (const float*)d_in[3];
    const float* dpw    = (const float*)d_in[4];
    float* out = (float*)d_out;

    router_k<<<TT, 256>>>(x, gate_w);
    zero_k<<<1, 32>>>();
    scatter_k<<<(TT + 255) / 256, 256>>>();
    gateup_mma<<<dim3(EE, II / 128, TT / 64), 256>>>(x, gpw, upw);
    down_mma<<<dim3(EE, HH / 128, TT / 64), 256>>>(dpw);
    combine_k<<<(TT * HH + 255) / 256, 256>>>(out);
}

// round 8
// speedup vs baseline: 2.4488x; 1.0427x over previous
#include <cuda_runtime.h>
#include <math.h>
#include <stdint.h>

#define TT 1024
#define HH 2048
#define II 1024
#define EE 32

// ---------------- scratch (device globals; no allocs) ----------------
__device__ __align__(256) int   g_top2_idx[TT * 2];
__device__ __align__(256) float g_top2_w[TT * 2];
__device__ __align__(256) int   g_cnt[EE];
__device__ __align__(256) int   g_toklist[EE * TT];          // packed (t<<1)|slot
__device__ __align__(256) float g_act[TT * 2 * II];          // 8 MB
__device__ __align__(256) float g_partial[2 * TT * HH];      // 16 MB

// ---------------- tf32 mma.sync helpers ----------------
__device__ __forceinline__ uint32_t f2tf(float f) {
    uint32_t r; asm("cvt.rna.tf32.f32 %0, %1;" : "=r"(r) : "f"(f)); return r;
}
__device__ __forceinline__ void mma1688(float* d, const uint32_t* a, const uint32_t* b) {
    asm volatile(
        "mma.sync.aligned.m16n8k8.row.col.f32.tf32.tf32.f32 "
        "{%0,%1,%2,%3}, {%4,%5,%6,%7}, {%8,%9}, {%0,%1,%2,%3};"
        : "+f"(d[0]), "+f"(d[1]), "+f"(d[2]), "+f"(d[3])
        : "r"(a[0]), "r"(a[1]), "r"(a[2]), "r"(a[3]), "r"(b[0]), "r"(b[1]));
}
__device__ __forceinline__ uint4 cvt4(float4 v) {
    uint4 o; o.x = f2tf(v.x); o.y = f2tf(v.y); o.z = f2tf(v.z); o.w = f2tf(v.w);
    return o;
}

#define LDW 36   // 32 k + 4 pad: frag LDS bank = 4g+tig, conflict-free

// ---------------- 1. router ----------------
__global__ __launch_bounds__(256) void router_k(const float* __restrict__ x,
                                                const float* __restrict__ gw) {
    __shared__ float xs[HH];
    __shared__ float lg[EE];
    int t = blockIdx.x;
    const float* xr = x + (size_t)t * HH;
    for (int i = threadIdx.x; i < HH; i += 256) xs[i] = xr[i];
    __syncthreads();
    int w = threadIdx.x >> 5, lane = threadIdx.x & 31;
    for (int e = w; e < EE; e += 8) {
        const float* g = gw + (size_t)e * HH;
        float s = 0.f;
        for (int h = lane; h < HH; h += 32) s += xs[h] * g[h];
        #pragma unroll
        for (int o = 16; o; o >>= 1) s += __shfl_xor_sync(0xffffffffu, s, o);
        if (!lane) lg[e] = s;
    }
    __syncthreads();
    if (threadIdx.x == 0) {
        float m1 = -1e30f, m2 = -1e30f; int i1 = 0, i2 = 1;
        for (int e = 0; e < EE; e++) {
            float v = lg[e];
            if (v > m1)      { m2 = m1; i2 = i1; m1 = v; i1 = e; }
            else if (v > m2) { m2 = v; i2 = e; }
        }
        float q = expf(m2 - m1);
        float w1 = 1.f / (1.f + q);
        g_top2_idx[2 * t] = i1;  g_top2_idx[2 * t + 1] = i2;
        g_top2_w[2 * t] = w1;    g_top2_w[2 * t + 1] = 1.f - w1;
    }
}

// ---------------- 2. per-expert token lists ----------------
__global__ void zero_k() { if (threadIdx.x < EE) g_cnt[threadIdx.x] = 0; }

__global__ void scatter_k() {
    int t = blockIdx.x * blockDim.x + threadIdx.x;
    if (t >= TT) return;
    #pragma unroll
    for (int s = 0; s < 2; s++) {
        int e = g_top2_idx[2 * t + s];
        int pos = atomicAdd(&g_cnt[e], 1);
        g_toklist[e * TT + pos] = (t << 1) | s;
    }
}

// ---------------- 3. gate+up grouped GEMM: 128tok x 64i x BK32, double-buffered ----
// grid (E, II/64, TT/128); block 256 = 8 warps (4 m x 2 n), warp 32x32 per matrix.
// dyn smem per buffer: A 128*LDW, G 64*LDW, U 64*LDW u32; two buffers.
__global__ __launch_bounds__(256) void gateup_mma(const float* __restrict__ x,
                                                  const float* __restrict__ gw,
                                                  const float* __restrict__ uw) {
    int e = blockIdx.x;
    int cnt = g_cnt[e];
    int m0 = blockIdx.z << 7;
    if (m0 >= cnt) return;
    int i0 = blockIdx.y << 6;

    extern __shared__ uint32_t dsm[];
    const int ASZ = 128 * LDW, BSZ = 64 * LDW, BUF = ASZ + 2 * BSZ;

    __shared__ int   stok[128];
    __shared__ float swt[128];

    int tid = threadIdx.x, wid = tid >> 5, lane = tid & 31;
    int g = lane >> 2, tig = lane & 3;
    int m_base = (wid >> 1) * 32;        // 0..96
    int n_base = (wid & 1) * 32;         // 0 or 32

    if (tid < 128) {
        int m = m0 + tid;
        if (m < cnt) { int p = g_toklist[e * TT + m]; stok[tid] = p; swt[tid] = g_top2_w[p]; }
        else         { stok[tid] = g_toklist[e * TT]; swt[tid] = 0.f; }
    }
    __syncthreads();

    // staging: A 4 float4/thread (128 rows x 8 chunks), G/U 2 float4/thread (64 rows)
    const float* ap[4]; uint32_t soa[4];
    #pragma unroll
    for (int c = 0; c < 4; c++) {
        int f = c * 256 + tid, row = f >> 3, q = f & 7;
        ap[c]  = x + (size_t)(stok[row] >> 1) * HH + q * 4;
        soa[c] = row * LDW + q * 4;
    }
    const float* gp[2]; const float* up_[2]; uint32_t sob[2];
    #pragma unroll
    for (int c = 0; c < 2; c++) {
        int f = c * 256 + tid, row = f >> 3, q = f & 7;
        gp[c]  = gw + ((size_t)e * II + i0 + row) * HH + q * 4;
        up_[c] = uw + ((size_t)e * II + i0 + row) * HH + q * 4;
        sob[c] = row * LDW + q * 4;
    }

    float accG[2][4][4], accU[2][4][4];
    #pragma unroll
    for (int mt = 0; mt < 2; mt++)
        #pragma unroll
        for (int nt = 0; nt < 4; nt++)
            #pragma unroll
            for (int j = 0; j < 4; j++) { accG[mt][nt][j] = 0.f; accU[mt][nt][j] = 0.f; }

    const int NIT = HH / 32;
    float4 av[4], gv[2], uv[2];
    #pragma unroll
    for (int c = 0; c < 4; c++) av[c] = *(const float4*)(ap[c]);
    #pragma unroll
    for (int c = 0; c < 2; c++) { gv[c] = *(const float4*)(gp[c]);
                                  uv[c] = *(const float4*)(up_[c]); }

    for (int it = 0; it < NIT; it++) {
        uint32_t* B = dsm + (it & 1) * BUF;
        #pragma unroll
        for (int c = 0; c < 4; c++) *(uint4*)&B[soa[c]] = cvt4(av[c]);
        #pragma unroll
        for (int c = 0; c < 2; c++) { *(uint4*)&B[ASZ + sob[c]]       = cvt4(gv[c]);
                                      *(uint4*)&B[ASZ + BSZ + sob[c]] = cvt4(uv[c]); }
        __syncthreads();
        if (it + 1 < NIT) {                  // prefetch next tile while MMA runs
            int k0 = (it + 1) * 32;
            #pragma unroll
            for (int c = 0; c < 4; c++) av[c] = *(const float4*)(ap[c] + k0);
            #pragma unroll
            for (int c = 0; c < 2; c++) { gv[c] = *(const float4*)(gp[c] + k0);
                                          uv[c] = *(const float4*)(up_[c] + k0); }
        }
        #pragma unroll
        for (int ks = 0; ks < 4; ks++) {
            int kk = ks * 8;
            uint32_t af[2][4];
            #pragma unroll
            for (int mt = 0; mt < 2; mt++) {
                int rb = m_base + mt * 16 + g;
                af[mt][0] = B[rb * LDW + kk + tig];
                af[mt][1] = B[(rb + 8) * LDW + kk + tig];
                af[mt][2] = B[rb * LDW + kk + tig + 4];
                af[mt][3] = B[(rb + 8) * LDW + kk + tig + 4];
            }
            #pragma unroll
            for (int nt = 0; nt < 4; nt++) {
                int cb = (n_base + nt * 8 + g) * LDW + kk + tig;
                uint32_t bg[2] = { B[ASZ + cb], B[ASZ + cb + 4] };
                uint32_t bu[2] = { B[ASZ + BSZ + cb], B[ASZ + BSZ + cb + 4] };
                #pragma unroll
                for (int mt = 0; mt < 2; mt++) {
                    mma1688(accG[mt][nt], af[mt], bg);
                    mma1688(accU[mt][nt], af[mt], bu);
                }
            }
        }
    }

    // fused SwiGLU + routing-weight epilogue
    #pragma unroll
    for (int mt = 0; mt < 2; mt++) {
        int r0 = m_base + mt * 16 + g;
        #pragma unroll
        for (int half = 0; half < 2; half++) {
            int rr = r0 + half * 8;
            if (m0 + rr < cnt) {
                int p = stok[rr]; float wgt = swt[rr];
                float* orow = g_act + (size_t)p * II + i0;
                #pragma unroll
                for (int nt = 0; nt < 4; nt++) {
                    float g0 = accG[mt][nt][half * 2], g1 = accG[mt][nt][half * 2 + 1];
                    float u0 = accU[mt][nt][half * 2], u1 = accU[mt][nt][half * 2 + 1];
                    float2 o;
                    o.x = (g0 / (1.f + expf(-g0))) * u0 * wgt;
                    o.y = (g1 / (1.f + expf(-g1))) * u1 * wgt;
                    *(float2*)(orow + n_base + nt * 8 + tig * 2) = o;
                }
            }
        }
    }
}

// ---------------- 4. down grouped GEMM: 128tok x 64h x BK32, double-buffered ----
// grid (E, HH/64, TT/128); same warp layout; K = II.
__global__ __launch_bounds__(256) void down_mma(const float* __restrict__ dw) {
    int e = blockIdx.x;
    int cnt = g_cnt[e];
    int m0 = blockIdx.z << 7;
    if (m0 >= cnt) return;
    int h0 = blockIdx.y << 6;

    extern __shared__ uint32_t dsm[];
    const int ASZ = 128 * LDW, BSZ = 64 * LDW, BUF = ASZ + BSZ;

    __shared__ int stok[128];

    int tid = threadIdx.x, wid = tid >> 5, lane = tid & 31;
    int g = lane >> 2, tig = lane & 3;
    int m_base = (wid >> 1) * 32;
    int n_base = (wid & 1) * 32;

    if (tid < 128) {
        int m = m0 + tid;
        stok[tid] = (m < cnt) ? g_toklist[e * TT + m] : g_toklist[e * TT];
    }
    __syncthreads();

    const float* ap[4]; uint32_t soa[4];
    #pragma unroll
    for (int c = 0; c < 4; c++) {
        int f = c * 256 + tid, row = f >> 3, q = f & 7;
        ap[c]  = g_act + (size_t)stok[row] * II + q * 4;
        soa[c] = row * LDW + q * 4;
    }
    const float* bp[2]; uint32_t sob[2];
    #pragma unroll
    for (int c = 0; c < 2; c++) {
        int f = c * 256 + tid, row = f >> 3, q = f & 7;
        bp[c]  = dw + ((size_t)e * HH + h0 + row) * II + q * 4;
        sob[c] = row * LDW + q * 4;
    }

    float acc[2][4][4];
    #pragma unroll
    for (int mt = 0; mt < 2; mt++)
        #pragma unroll
        for (int nt = 0; nt < 4; nt++)
            #pragma unroll
            for (int j = 0; j < 4; j++) acc[mt][nt][j] = 0.f;

    const int NIT = II / 32;
    float4 av[4], bv[2];
    #pragma unroll
    for (int c = 0; c < 4; c++) av[c] = *(const float4*)(ap[c]);
    #pragma unroll
    for (int c = 0; c < 2; c++) bv[c] = *(const float4*)(bp[c]);

    for (int it = 0; it < NIT; it++) {
        uint32_t* B = dsm + (it & 1) * BUF;
        #pragma unroll
        for (int c = 0; c < 4; c++) *(uint4*)&B[soa[c]] = cvt4(av[c]);
        #pragma unroll
        for (int c = 0; c < 2; c++) *(uint4*)&B[ASZ + sob[c]] = cvt4(bv[c]);
        __syncthreads();
        if (it + 1 < NIT) {
            int k0 = (it + 1) * 32;
            #pragma unroll
            for (int c = 0; c < 4; c++) av[c] = *(const float4*)(ap[c] + k0);
            #pragma unroll
            for (int c = 0; c < 2; c++) bv[c] = *(const float4*)(bp[c] + k0);
        }
        #pragma unroll
        for (int ks = 0; ks < 4; ks++) {
            int kk = ks * 8;
            uint32_t af[2][4];
            #pragma unroll
            for (int mt = 0; mt < 2; mt++) {
                int rb = m_base + mt * 16 + g;
                af[mt][0] = B[rb * LDW + kk + tig];
                af[mt][1] = B[(rb + 8) * LDW + kk + tig];
                af[mt][2] = B[rb * LDW + kk + tig + 4];
                af[mt][3] = B[(rb + 8) * LDW + kk + tig + 4];
            }
            #pragma unroll
            for (int nt = 0; nt < 4; nt++) {
                int cb = (n_base + nt * 8 + g) * LDW + kk + tig;
                uint32_t bb[2] = { B[ASZ + cb], B[ASZ + cb + 4] };
                #pragma unroll
                for (int mt = 0; mt < 2; mt++) mma1688(acc[mt][nt], af[mt], bb);
            }
        }
    }

    #pragma unroll
    for (int mt = 0; mt < 2; mt++) {
        int r0 = m_base + mt * 16 + g;
        #pragma unroll
        for (int half = 0; half < 2; half++) {
            int rr = r0 + half * 8;
            if (m0 + rr < cnt) {
                int p = stok[rr];
                int t = p >> 1, s = p & 1;
                float* orow = g_partial + (size_t)s * TT * HH + (size_t)t * HH + h0;
                #pragma unroll
                for (int nt = 0; nt < 4; nt++) {
                    float2 o;
                    o.x = acc[mt][nt][half * 2];
                    o.y = acc[mt][nt][half * 2 + 1];
                    *(float2*)(orow + n_base + nt * 8 + tig * 2) = o;
                }
            }
        }
    }
}

// ---------------- 5. combine slot partials ----------------
__global__ void combine_k(float* __restrict__ out) {
    int i = blockIdx.x * 256 + threadIdx.x;
    if (i < TT * HH) out[i] = g_partial[i] + g_partial[TT * HH + i];
}

// ---------------- launch ----------------
extern "C" void kernel_launch(void* const* d_in, const int* in_sizes, int n_in,
                              void* d_out, int out_size) {
    const float* x      = (const float*)d_in[0];
    const float* gate_w = (const float*)d_in[1];
    const float* gpw    = (const float*)d_in[2];
    const float* upw    = (const float*)d_in[3];
    const float* dpw    = (const float*)d_in[4];
    float* out = (float*)d_out;

    const int GU_SMEM = 2 * (128 + 64 + 64) * LDW * 4;   // 73728 B
    const int DN_SMEM = 2 * (128 + 64) * LDW * 4;        // 55296 B
    cudaFuncSetAttribute(gateup_mma, cudaFuncAttributeMaxDynamicSharedMemorySize, GU_SMEM);
    cudaFuncSetAttribute(down_mma,   cudaFuncAttributeMaxDynamicSharedMemorySize, DN_SMEM);

    router_k<<<TT, 256>>>(x, gate_w);
    zero_k<<<1, 32>>>();
    scatter_k<<<(TT + 255) / 256, 256>>>();
    gateup_mma<<<dim3(EE, II / 64, TT / 128), 256, GU_SMEM>>>(x, gpw, upw);
    down_mma<<<dim3(EE, HH / 64, TT / 128), 256, DN_SMEM>>>(dpw);
    combine_k<<<(TT * HH + 255) / 256, 256>>>(out);
}